// round 3
// baseline (speedup 1.0000x reference)
#include <cuda_runtime.h>

// Problem constants
#define BATCH      32768
#define OBS_DIM    576
#define NUM_OBJS   32
#define D_MODEL    128
#define ROWS_PER_BLK 4            // batch rows per block
#define TILE_M     128            // 4 rows * 32 objects
#define HS         132            // padded smem row stride (floats)

// Precomputed Mt[c][d] = sum_e Uq[e][c] * Ur[e][d]
// so that qu[d] = sum_c query[c] * Mt[c][d]  (folds Uq and Ur into one matvec)
__device__ float g_Mt[D_MODEL * D_MODEL];

__global__ void precompute_mt_kernel(const float* __restrict__ Uq,
                                     const float* __restrict__ Ur) {
    __shared__ float uqc[D_MODEL];
    const int c = blockIdx.x;      // 0..127
    const int t = threadIdx.x;     // 0..127
    uqc[t] = Uq[t * D_MODEL + c];  // Uq[e][c]
    __syncthreads();
    float acc = 0.f;
#pragma unroll 8
    for (int e = 0; e < D_MODEL; e++)
        acc = fmaf(uqc[e], Ur[e * D_MODEL + t], acc);
    g_Mt[c * D_MODEL + t] = acc;
}

// ---------------------------------------------------------------------------
// Fused kernel: per block, 4 batch rows (128 object-rows).
//   GEMM1: h1 = relu(feats @ W1^T + b1)     K=15
//   GEMM2: h2 = relu(h1 @ W2^T + b2)        K=128
//   GEMM3: x_real = (h2 @ W3^T + b3) * mask K=128
//   attention epilogue + output assembly
// All intermediates live in smem as transposed tiles hT[d][m].
// ---------------------------------------------------------------------------
extern __shared__ float smem[];

__global__ __launch_bounds__(256, 1)
void fused_base_attention_kernel(const float* __restrict__ obs,
                                 const float* __restrict__ W1,
                                 const float* __restrict__ b1,
                                 const float* __restrict__ W2,
                                 const float* __restrict__ b2,
                                 const float* __restrict__ W3,
                                 const float* __restrict__ b3,
                                 float* __restrict__ out) {
    // ---- smem layout (floats) ----
    float* xsT    = smem;                 // 16 x HS   : feature f (0..14) + mask (15), [f][m]
    float* w1T    = xsT + 16 * HS;        // 16 x 128  : w1T[f][d] = W1[d][f]
    float* w2T    = w1T + 16 * D_MODEL;   // 128 x HS  : w2T[k][e] = W2[e][k]
    float* w3T    = w2T + D_MODEL * HS;   // 128 x HS
    float* hT     = w3T + D_MODEL * HS;   // 128 x HS  : current activation (transposed)
    float* bias   = hT + D_MODEL * HS;    // 3 x 128
    float* querys = bias + 3 * D_MODEL;   // 4 x 128
    float* qus    = querys + 4 * D_MODEL; // 4 x 128
    float* wsoft  = qus + 4 * D_MODEL;    // 4 x 32
    float* msum   = wsoft + 4 * 32;       // 4
    float* oat    = msum + 4;             // 4 x 128

    const int tid  = threadIdx.x;
    const int tm   = tid >> 4;            // 0..15  (row group: m = 8*tm .. )
    const int tn   = tid & 15;            // 0..15  (col group: e = 8*tn .. )
    const int blk  = blockIdx.x;
    const int base = blk * ROWS_PER_BLK;  // first batch row

    // ---- load W1 transposed ----
    for (int idx = tid; idx < D_MODEL * 15; idx += 256) {
        int d = idx / 15, f = idx % 15;
        w1T[f * D_MODEL + d] = W1[idx];
    }
    // ---- load W2, W3 transposed (float4 global reads, scatter smem writes) ----
    for (int idx = tid; idx < (D_MODEL * D_MODEL) / 4; idx += 256) {
        float4 v2 = ((const float4*)W2)[idx];
        float4 v3 = ((const float4*)W3)[idx];
        int flat = idx * 4;
        int e = flat >> 7;          // output dim
        int k = flat & 127;         // input dim (4 consecutive)
        w2T[(k + 0) * HS + e] = v2.x;  w2T[(k + 1) * HS + e] = v2.y;
        w2T[(k + 2) * HS + e] = v2.z;  w2T[(k + 3) * HS + e] = v2.w;
        w3T[(k + 0) * HS + e] = v3.x;  w3T[(k + 1) * HS + e] = v3.y;
        w3T[(k + 2) * HS + e] = v3.z;  w3T[(k + 3) * HS + e] = v3.w;
    }
    if (tid < D_MODEL) {
        bias[tid]               = b1[tid];
        bias[D_MODEL + tid]     = b2[tid];
        bias[2 * D_MODEL + tid] = b3[tid];
    }
    // ---- load attention slice: obs[b, 32:544] -> xsT[f][m] ----
    for (int q = tid; q < 512; q += 256) {          // 512 float4 = 4 rows x 128
        int r = q >> 7;                             // batch row within block
        int o = q & 127;                            // float4 index in row
        float4 v = ((const float4*)(obs + (base + r) * OBS_DIM + 32))[o];
        int n  = o >> 2;                            // object
        int fg = (o & 3) * 4;                       // feature base
        int m  = (r << 5) + n;
        xsT[(fg + 0) * HS + m] = v.x;
        xsT[(fg + 1) * HS + m] = v.y;
        xsT[(fg + 2) * HS + m] = v.z;
        xsT[(fg + 3) * HS + m] = v.w;
    }
    __syncthreads();

    float acc[8][8];

    // ================= GEMM1: K=15, relu, -> hT =================
    {
        const float* bv = bias + 8 * tn;
#pragma unroll
        for (int i = 0; i < 8; i++)
#pragma unroll
            for (int j = 0; j < 8; j++) acc[i][j] = bv[j];

        const float* pa = xsT + 8 * tm;
        const float* pb = w1T + 8 * tn;
#pragma unroll 3
        for (int k = 0; k < 15; k++) {
            float4 a0 = *(const float4*)(pa);
            float4 a1 = *(const float4*)(pa + 4);
            float4 c0 = *(const float4*)(pb);
            float4 c1 = *(const float4*)(pb + 4);
            float a[8] = {a0.x, a0.y, a0.z, a0.w, a1.x, a1.y, a1.z, a1.w};
            float b[8] = {c0.x, c0.y, c0.z, c0.w, c1.x, c1.y, c1.z, c1.w};
#pragma unroll
            for (int i = 0; i < 8; i++)
#pragma unroll
                for (int j = 0; j < 8; j++)
                    acc[i][j] = fmaf(a[i], b[j], acc[i][j]);
            pa += HS; pb += D_MODEL;
        }
        // hT not yet read by anyone: write directly (disjoint from xsT/w1T)
#pragma unroll
        for (int j = 0; j < 8; j++) {
            float* dst = hT + (8 * tn + j) * HS + 8 * tm;
            *(float4*)(dst)     = make_float4(fmaxf(acc[0][j], 0.f), fmaxf(acc[1][j], 0.f),
                                              fmaxf(acc[2][j], 0.f), fmaxf(acc[3][j], 0.f));
            *(float4*)(dst + 4) = make_float4(fmaxf(acc[4][j], 0.f), fmaxf(acc[5][j], 0.f),
                                              fmaxf(acc[6][j], 0.f), fmaxf(acc[7][j], 0.f));
        }
    }
    __syncthreads();

    // ================= GEMM2: K=128, relu, hT -> hT =================
    {
        const float* bv = bias + D_MODEL + 8 * tn;
#pragma unroll
        for (int i = 0; i < 8; i++)
#pragma unroll
            for (int j = 0; j < 8; j++) acc[i][j] = bv[j];

        const float* pa = hT + 8 * tm;
        const float* pb = w2T + 8 * tn;
#pragma unroll 2
        for (int k = 0; k < 128; k++) {
            float4 a0 = *(const float4*)(pa);
            float4 a1 = *(const float4*)(pa + 4);
            float4 c0 = *(const float4*)(pb);
            float4 c1 = *(const float4*)(pb + 4);
            float a[8] = {a0.x, a0.y, a0.z, a0.w, a1.x, a1.y, a1.z, a1.w};
            float b[8] = {c0.x, c0.y, c0.z, c0.w, c1.x, c1.y, c1.z, c1.w};
#pragma unroll
            for (int i = 0; i < 8; i++)
#pragma unroll
                for (int j = 0; j < 8; j++)
                    acc[i][j] = fmaf(a[i], b[j], acc[i][j]);
            pa += HS; pb += HS;
        }
        __syncthreads();   // all reads of hT done before overwrite
#pragma unroll
        for (int j = 0; j < 8; j++) {
            float* dst = hT + (8 * tn + j) * HS + 8 * tm;
            *(float4*)(dst)     = make_float4(fmaxf(acc[0][j], 0.f), fmaxf(acc[1][j], 0.f),
                                              fmaxf(acc[2][j], 0.f), fmaxf(acc[3][j], 0.f));
            *(float4*)(dst + 4) = make_float4(fmaxf(acc[4][j], 0.f), fmaxf(acc[5][j], 0.f),
                                              fmaxf(acc[6][j], 0.f), fmaxf(acc[7][j], 0.f));
        }
    }
    __syncthreads();

    // ================= GEMM3: K=128, +b3, *mask, hT -> hT (x_realT) =================
    {
        const float* bv = bias + 2 * D_MODEL + 8 * tn;
#pragma unroll
        for (int i = 0; i < 8; i++)
#pragma unroll
            for (int j = 0; j < 8; j++) acc[i][j] = bv[j];

        const float* pa = hT + 8 * tm;
        const float* pb = w3T + 8 * tn;
#pragma unroll 2
        for (int k = 0; k < 128; k++) {
            float4 a0 = *(const float4*)(pa);
            float4 a1 = *(const float4*)(pa + 4);
            float4 c0 = *(const float4*)(pb);
            float4 c1 = *(const float4*)(pb + 4);
            float a[8] = {a0.x, a0.y, a0.z, a0.w, a1.x, a1.y, a1.z, a1.w};
            float b[8] = {c0.x, c0.y, c0.z, c0.w, c1.x, c1.y, c1.z, c1.w};
#pragma unroll
            for (int i = 0; i < 8; i++)
#pragma unroll
                for (int j = 0; j < 8; j++)
                    acc[i][j] = fmaf(a[i], b[j], acc[i][j]);
            pa += HS; pb += HS;
        }
        // per-row mask values
        float4 m0 = *(const float4*)&xsT[15 * HS + 8 * tm];
        float4 m1 = *(const float4*)&xsT[15 * HS + 8 * tm + 4];
        float msk[8] = {m0.x, m0.y, m0.z, m0.w, m1.x, m1.y, m1.z, m1.w};
        __syncthreads();
#pragma unroll
        for (int j = 0; j < 8; j++) {
            float* dst = hT + (8 * tn + j) * HS + 8 * tm;
            *(float4*)(dst)     = make_float4(acc[0][j] * msk[0], acc[1][j] * msk[1],
                                              acc[2][j] * msk[2], acc[3][j] * msk[3]);
            *(float4*)(dst + 4) = make_float4(acc[4][j] * msk[4], acc[5][j] * msk[5],
                                              acc[6][j] * msk[6], acc[7][j] * msk[7]);
        }
    }
    __syncthreads();

    // ================= attention epilogue =================
    // mask sums
    if (tid < 4) {
        float s = 0.f;
        const float* mr = xsT + 15 * HS + 32 * tid;
#pragma unroll
        for (int n = 0; n < 32; n++) s += mr[n];
        msum[tid] = s + 1e-5f;
    }
    __syncthreads();

    // query[r][d] = sum_n x_realT[d][32r+n] / msum[r]
    {
        int r  = tid >> 6;
        int d0 = (tid & 63) * 2;
        float inv = 1.0f / msum[r];
#pragma unroll
        for (int dd = 0; dd < 2; dd++) {
            int d = d0 + dd;
            const float* row = hT + d * HS + 32 * r;
            float s = 0.f;
#pragma unroll
            for (int n = 0; n < 32; n += 4) {
                float4 v = *(const float4*)&row[n];
                s += v.x + v.y + v.z + v.w;
            }
            querys[r * D_MODEL + d] = s * inv;
        }
    }
    __syncthreads();

    // qu[r][d'] = sum_c query[r][c] * Mt[c][d']   (Mt global, L2-resident, coalesced)
    if (tid < 128) {
        float a0 = 0.f, a1 = 0.f, a2 = 0.f, a3 = 0.f;
#pragma unroll 4
        for (int c = 0; c < 128; c++) {
            float mv = g_Mt[c * D_MODEL + tid];
            a0 = fmaf(querys[c],               mv, a0);
            a1 = fmaf(querys[D_MODEL + c],     mv, a1);
            a2 = fmaf(querys[2 * D_MODEL + c], mv, a2);
            a3 = fmaf(querys[3 * D_MODEL + c], mv, a3);
        }
        qus[tid]               = a0;
        qus[D_MODEL + tid]     = a1;
        qus[2 * D_MODEL + tid] = a2;
        qus[3 * D_MODEL + tid] = a3;
    }
    __syncthreads();

    // logits + warp softmax (warp == batch row, lane == object)
    if (tid < 128) {
        int r = tid >> 5;
        int m = tid;              // 32*r + n == tid
        float s = 0.f;
#pragma unroll 4
        for (int d = 0; d < 128; d++)
            s = fmaf(qus[r * D_MODEL + d], hT[d * HS + m], s);
        float mk = xsT[15 * HS + m];
        float logit = s + (1.0f - mk) * -1e9f;
        float mx = logit;
#pragma unroll
        for (int off = 16; off; off >>= 1)
            mx = fmaxf(mx, __shfl_xor_sync(0xffffffffu, mx, off));
        float e = expf(logit - mx);
        float sum = e;
#pragma unroll
        for (int off = 16; off; off >>= 1)
            sum += __shfl_xor_sync(0xffffffffu, sum, off);
        wsoft[tid] = e / sum;
    }
    __syncthreads();

    // out_att[r][d] = sum_n w[r][n] * x_realT[d][32r+n]
    {
        int r  = tid >> 6;
        int d0 = (tid & 63) * 2;
#pragma unroll
        for (int dd = 0; dd < 2; dd++) {
            int d = d0 + dd;
            const float* xr = hT + d * HS + 32 * r;
            const float* wr = wsoft + 32 * r;
            float s = 0.f;
#pragma unroll
            for (int n = 0; n < 32; n++) s = fmaf(wr[n], xr[n], s);
            oat[r * D_MODEL + d] = s;
        }
    }
    __syncthreads();

    // output: [aux(64) | out_att(128)] per row
    for (int idx = tid; idx < ROWS_PER_BLK * 192; idx += 256) {
        int r = idx / 192;
        int c = idx - r * 192;
        int b = base + r;
        float v;
        if (c < 32)       v = obs[b * OBS_DIM + c];            // obs[:, :32]
        else if (c < 64)  v = obs[b * OBS_DIM + 512 + c];      // obs[:, 544:576]
        else              v = oat[r * D_MODEL + (c - 64)];
        out[b * 192 + c] = v;
    }
}

// ---------------------------------------------------------------------------
extern "C" void kernel_launch(void* const* d_in, const int* in_sizes, int n_in,
                              void* d_out, int out_size) {
    const float* obs = (const float*)d_in[0];
    const float* W1  = (const float*)d_in[1];
    const float* b1  = (const float*)d_in[2];
    const float* W2  = (const float*)d_in[3];
    const float* b2  = (const float*)d_in[4];
    const float* W3  = (const float*)d_in[5];
    const float* b3  = (const float*)d_in[6];
    const float* Uq  = (const float*)d_in[7];
    const float* Ur  = (const float*)d_in[8];
    float* out = (float*)d_out;

    // smem size in bytes (must match layout above)
    const size_t smem_bytes =
        (16 * HS + 16 * D_MODEL + 3 * (D_MODEL * HS) + 3 * D_MODEL +
         4 * D_MODEL + 4 * D_MODEL + 4 * 32 + 4 + 4 * D_MODEL) * sizeof(float);

    cudaFuncSetAttribute(fused_base_attention_kernel,
                         cudaFuncAttributeMaxDynamicSharedMemorySize,
                         (int)smem_bytes);

    precompute_mt_kernel<<<D_MODEL, D_MODEL>>>(Uq, Ur);
    fused_base_attention_kernel<<<BATCH / ROWS_PER_BLK, 256, smem_bytes>>>(
        obs, W1, b1, W2, b2, W3, b3, out);
}

// round 4
// speedup vs baseline: 1.0004x; 1.0004x over previous
#include <cuda_runtime.h>

// Problem constants
#define BATCH      32768
#define OBS_DIM    576
#define NUM_OBJS   32
#define D_MODEL    128
#define ROWS_PER_BLK 4            // batch rows per block
#define TILE_M     128            // 4 rows * 32 objects
#define HS         132            // padded smem row stride (floats)

// Precomputed Mt[c][d] = sum_e Uq[e][c] * Ur[e][d]
// so that qu[d] = sum_c query[c] * Mt[c][d]  (folds Uq and Ur into one matvec)
__device__ float g_Mt[D_MODEL * D_MODEL];

__global__ void precompute_mt_kernel(const float* __restrict__ Uq,
                                     const float* __restrict__ Ur) {
    __shared__ float uqc[D_MODEL];
    const int c = blockIdx.x;      // 0..127
    const int t = threadIdx.x;     // 0..127
    uqc[t] = Uq[t * D_MODEL + c];  // Uq[e][c]
    __syncthreads();
    float acc = 0.f;
#pragma unroll 8
    for (int e = 0; e < D_MODEL; e++)
        acc = fmaf(uqc[e], Ur[e * D_MODEL + t], acc);
    g_Mt[c * D_MODEL + t] = acc;
}

// ---------------------------------------------------------------------------
// Fused kernel: per block, 4 batch rows (128 object-rows).
//   GEMM1: h1 = relu(feats @ W1^T + b1)     K=15
//   GEMM2: h2 = relu(h1 @ W2^T + b2)        K=128
//   GEMM3: x_real = (h2 @ W3^T + b3) * mask K=128
//   attention epilogue + output assembly
// All intermediates live in smem as transposed tiles hT[d][m].
// ---------------------------------------------------------------------------
extern __shared__ float smem[];

__global__ __launch_bounds__(256, 1)
void fused_base_attention_kernel(const float* __restrict__ obs,
                                 const float* __restrict__ W1,
                                 const float* __restrict__ b1,
                                 const float* __restrict__ W2,
                                 const float* __restrict__ b2,
                                 const float* __restrict__ W3,
                                 const float* __restrict__ b3,
                                 float* __restrict__ out) {
    // ---- smem layout (floats) ----
    float* xsT    = smem;                 // 16 x HS   : feature f (0..14) + mask (15), [f][m]
    float* w1T    = xsT + 16 * HS;        // 16 x 128  : w1T[f][d] = W1[d][f]
    float* w2T    = w1T + 16 * D_MODEL;   // 128 x HS  : w2T[k][e] = W2[e][k]
    float* w3T    = w2T + D_MODEL * HS;   // 128 x HS
    float* hT     = w3T + D_MODEL * HS;   // 128 x HS  : current activation (transposed)
    float* bias   = hT + D_MODEL * HS;    // 3 x 128
    float* querys = bias + 3 * D_MODEL;   // 4 x 128
    float* qus    = querys + 4 * D_MODEL; // 4 x 128
    float* wsoft  = qus + 4 * D_MODEL;    // 4 x 32
    float* msum   = wsoft + 4 * 32;       // 4
    float* oat    = msum + 4;             // 4 x 128

    const int tid  = threadIdx.x;
    const int tm   = tid >> 4;            // 0..15  (row group: m = 8*tm .. )
    const int tn   = tid & 15;            // 0..15  (col group: e = 8*tn .. )
    const int blk  = blockIdx.x;
    const int base = blk * ROWS_PER_BLK;  // first batch row

    // ---- load W1 transposed ----
    for (int idx = tid; idx < D_MODEL * 15; idx += 256) {
        int d = idx / 15, f = idx % 15;
        w1T[f * D_MODEL + d] = W1[idx];
    }
    // ---- load W2, W3 transposed (float4 global reads, scatter smem writes) ----
    for (int idx = tid; idx < (D_MODEL * D_MODEL) / 4; idx += 256) {
        float4 v2 = ((const float4*)W2)[idx];
        float4 v3 = ((const float4*)W3)[idx];
        int flat = idx * 4;
        int e = flat >> 7;          // output dim
        int k = flat & 127;         // input dim (4 consecutive)
        w2T[(k + 0) * HS + e] = v2.x;  w2T[(k + 1) * HS + e] = v2.y;
        w2T[(k + 2) * HS + e] = v2.z;  w2T[(k + 3) * HS + e] = v2.w;
        w3T[(k + 0) * HS + e] = v3.x;  w3T[(k + 1) * HS + e] = v3.y;
        w3T[(k + 2) * HS + e] = v3.z;  w3T[(k + 3) * HS + e] = v3.w;
    }
    if (tid < D_MODEL) {
        bias[tid]               = b1[tid];
        bias[D_MODEL + tid]     = b2[tid];
        bias[2 * D_MODEL + tid] = b3[tid];
    }
    // ---- load attention slice: obs[b, 32:544] -> xsT[f][m] ----
    for (int q = tid; q < 512; q += 256) {          // 512 float4 = 4 rows x 128
        int r = q >> 7;                             // batch row within block
        int o = q & 127;                            // float4 index in row
        float4 v = ((const float4*)(obs + (base + r) * OBS_DIM + 32))[o];
        int n  = o >> 2;                            // object
        int fg = (o & 3) * 4;                       // feature base
        int m  = (r << 5) + n;
        xsT[(fg + 0) * HS + m] = v.x;
        xsT[(fg + 1) * HS + m] = v.y;
        xsT[(fg + 2) * HS + m] = v.z;
        xsT[(fg + 3) * HS + m] = v.w;
    }
    __syncthreads();

    float acc[8][8];

    // ================= GEMM1: K=15, relu, -> hT =================
    {
        const float* bv = bias + 8 * tn;
#pragma unroll
        for (int i = 0; i < 8; i++)
#pragma unroll
            for (int j = 0; j < 8; j++) acc[i][j] = bv[j];

        const float* pa = xsT + 8 * tm;
        const float* pb = w1T + 8 * tn;
#pragma unroll 3
        for (int k = 0; k < 15; k++) {
            float4 a0 = *(const float4*)(pa);
            float4 a1 = *(const float4*)(pa + 4);
            float4 c0 = *(const float4*)(pb);
            float4 c1 = *(const float4*)(pb + 4);
            float a[8] = {a0.x, a0.y, a0.z, a0.w, a1.x, a1.y, a1.z, a1.w};
            float b[8] = {c0.x, c0.y, c0.z, c0.w, c1.x, c1.y, c1.z, c1.w};
#pragma unroll
            for (int i = 0; i < 8; i++)
#pragma unroll
                for (int j = 0; j < 8; j++)
                    acc[i][j] = fmaf(a[i], b[j], acc[i][j]);
            pa += HS; pb += D_MODEL;
        }
        // hT not yet read by anyone: write directly (disjoint from xsT/w1T)
#pragma unroll
        for (int j = 0; j < 8; j++) {
            float* dst = hT + (8 * tn + j) * HS + 8 * tm;
            *(float4*)(dst)     = make_float4(fmaxf(acc[0][j], 0.f), fmaxf(acc[1][j], 0.f),
                                              fmaxf(acc[2][j], 0.f), fmaxf(acc[3][j], 0.f));
            *(float4*)(dst + 4) = make_float4(fmaxf(acc[4][j], 0.f), fmaxf(acc[5][j], 0.f),
                                              fmaxf(acc[6][j], 0.f), fmaxf(acc[7][j], 0.f));
        }
    }
    __syncthreads();

    // ================= GEMM2: K=128, relu, hT -> hT =================
    {
        const float* bv = bias + D_MODEL + 8 * tn;
#pragma unroll
        for (int i = 0; i < 8; i++)
#pragma unroll
            for (int j = 0; j < 8; j++) acc[i][j] = bv[j];

        const float* pa = hT + 8 * tm;
        const float* pb = w2T + 8 * tn;
#pragma unroll 2
        for (int k = 0; k < 128; k++) {
            float4 a0 = *(const float4*)(pa);
            float4 a1 = *(const float4*)(pa + 4);
            float4 c0 = *(const float4*)(pb);
            float4 c1 = *(const float4*)(pb + 4);
            float a[8] = {a0.x, a0.y, a0.z, a0.w, a1.x, a1.y, a1.z, a1.w};
            float b[8] = {c0.x, c0.y, c0.z, c0.w, c1.x, c1.y, c1.z, c1.w};
#pragma unroll
            for (int i = 0; i < 8; i++)
#pragma unroll
                for (int j = 0; j < 8; j++)
                    acc[i][j] = fmaf(a[i], b[j], acc[i][j]);
            pa += HS; pb += HS;
        }
        __syncthreads();   // all reads of hT done before overwrite
#pragma unroll
        for (int j = 0; j < 8; j++) {
            float* dst = hT + (8 * tn + j) * HS + 8 * tm;
            *(float4*)(dst)     = make_float4(fmaxf(acc[0][j], 0.f), fmaxf(acc[1][j], 0.f),
                                              fmaxf(acc[2][j], 0.f), fmaxf(acc[3][j], 0.f));
            *(float4*)(dst + 4) = make_float4(fmaxf(acc[4][j], 0.f), fmaxf(acc[5][j], 0.f),
                                              fmaxf(acc[6][j], 0.f), fmaxf(acc[7][j], 0.f));
        }
    }
    __syncthreads();

    // ================= GEMM3: K=128, +b3, *mask, hT -> hT (x_realT) =================
    {
        const float* bv = bias + 2 * D_MODEL + 8 * tn;
#pragma unroll
        for (int i = 0; i < 8; i++)
#pragma unroll
            for (int j = 0; j < 8; j++) acc[i][j] = bv[j];

        const float* pa = hT + 8 * tm;
        const float* pb = w3T + 8 * tn;
#pragma unroll 2
        for (int k = 0; k < 128; k++) {
            float4 a0 = *(const float4*)(pa);
            float4 a1 = *(const float4*)(pa + 4);
            float4 c0 = *(const float4*)(pb);
            float4 c1 = *(const float4*)(pb + 4);
            float a[8] = {a0.x, a0.y, a0.z, a0.w, a1.x, a1.y, a1.z, a1.w};
            float b[8] = {c0.x, c0.y, c0.z, c0.w, c1.x, c1.y, c1.z, c1.w};
#pragma unroll
            for (int i = 0; i < 8; i++)
#pragma unroll
                for (int j = 0; j < 8; j++)
                    acc[i][j] = fmaf(a[i], b[j], acc[i][j]);
            pa += HS; pb += HS;
        }
        // per-row mask values
        float4 m0 = *(const float4*)&xsT[15 * HS + 8 * tm];
        float4 m1 = *(const float4*)&xsT[15 * HS + 8 * tm + 4];
        float msk[8] = {m0.x, m0.y, m0.z, m0.w, m1.x, m1.y, m1.z, m1.w};
        __syncthreads();
#pragma unroll
        for (int j = 0; j < 8; j++) {
            float* dst = hT + (8 * tn + j) * HS + 8 * tm;
            *(float4*)(dst)     = make_float4(acc[0][j] * msk[0], acc[1][j] * msk[1],
                                              acc[2][j] * msk[2], acc[3][j] * msk[3]);
            *(float4*)(dst + 4) = make_float4(acc[4][j] * msk[4], acc[5][j] * msk[5],
                                              acc[6][j] * msk[6], acc[7][j] * msk[7]);
        }
    }
    __syncthreads();

    // ================= attention epilogue =================
    // mask sums
    if (tid < 4) {
        float s = 0.f;
        const float* mr = xsT + 15 * HS + 32 * tid;
#pragma unroll
        for (int n = 0; n < 32; n++) s += mr[n];
        msum[tid] = s + 1e-5f;
    }
    __syncthreads();

    // query[r][d] = sum_n x_realT[d][32r+n] / msum[r]
    {
        int r  = tid >> 6;
        int d0 = (tid & 63) * 2;
        float inv = 1.0f / msum[r];
#pragma unroll
        for (int dd = 0; dd < 2; dd++) {
            int d = d0 + dd;
            const float* row = hT + d * HS + 32 * r;
            float s = 0.f;
#pragma unroll
            for (int n = 0; n < 32; n += 4) {
                float4 v = *(const float4*)&row[n];
                s += v.x + v.y + v.z + v.w;
            }
            querys[r * D_MODEL + d] = s * inv;
        }
    }
    __syncthreads();

    // qu[r][d'] = sum_c query[r][c] * Mt[c][d']   (Mt global, L2-resident, coalesced)
    if (tid < 128) {
        float a0 = 0.f, a1 = 0.f, a2 = 0.f, a3 = 0.f;
#pragma unroll 4
        for (int c = 0; c < 128; c++) {
            float mv = g_Mt[c * D_MODEL + tid];
            a0 = fmaf(querys[c],               mv, a0);
            a1 = fmaf(querys[D_MODEL + c],     mv, a1);
            a2 = fmaf(querys[2 * D_MODEL + c], mv, a2);
            a3 = fmaf(querys[3 * D_MODEL + c], mv, a3);
        }
        qus[tid]               = a0;
        qus[D_MODEL + tid]     = a1;
        qus[2 * D_MODEL + tid] = a2;
        qus[3 * D_MODEL + tid] = a3;
    }
    __syncthreads();

    // logits + warp softmax (warp == batch row, lane == object)
    if (tid < 128) {
        int r = tid >> 5;
        int m = tid;              // 32*r + n == tid
        float s = 0.f;
#pragma unroll 4
        for (int d = 0; d < 128; d++)
            s = fmaf(qus[r * D_MODEL + d], hT[d * HS + m], s);
        float mk = xsT[15 * HS + m];
        float logit = s + (1.0f - mk) * -1e9f;
        float mx = logit;
#pragma unroll
        for (int off = 16; off; off >>= 1)
            mx = fmaxf(mx, __shfl_xor_sync(0xffffffffu, mx, off));
        float e = expf(logit - mx);
        float sum = e;
#pragma unroll
        for (int off = 16; off; off >>= 1)
            sum += __shfl_xor_sync(0xffffffffu, sum, off);
        wsoft[tid] = e / sum;
    }
    __syncthreads();

    // out_att[r][d] = sum_n w[r][n] * x_realT[d][32r+n]
    {
        int r  = tid >> 6;
        int d0 = (tid & 63) * 2;
#pragma unroll
        for (int dd = 0; dd < 2; dd++) {
            int d = d0 + dd;
            const float* xr = hT + d * HS + 32 * r;
            const float* wr = wsoft + 32 * r;
            float s = 0.f;
#pragma unroll
            for (int n = 0; n < 32; n++) s = fmaf(wr[n], xr[n], s);
            oat[r * D_MODEL + d] = s;
        }
    }
    __syncthreads();

    // output: [aux(64) | out_att(128)] per row
    for (int idx = tid; idx < ROWS_PER_BLK * 192; idx += 256) {
        int r = idx / 192;
        int c = idx - r * 192;
        int b = base + r;
        float v;
        if (c < 32)       v = obs[b * OBS_DIM + c];            // obs[:, :32]
        else if (c < 64)  v = obs[b * OBS_DIM + 512 + c];      // obs[:, 544:576]
        else              v = oat[r * D_MODEL + (c - 64)];
        out[b * 192 + c] = v;
    }
}

// ---------------------------------------------------------------------------
extern "C" void kernel_launch(void* const* d_in, const int* in_sizes, int n_in,
                              void* d_out, int out_size) {
    const float* obs = (const float*)d_in[0];
    const float* W1  = (const float*)d_in[1];
    const float* b1  = (const float*)d_in[2];
    const float* W2  = (const float*)d_in[3];
    const float* b2  = (const float*)d_in[4];
    const float* W3  = (const float*)d_in[5];
    const float* b3  = (const float*)d_in[6];
    const float* Uq  = (const float*)d_in[7];
    const float* Ur  = (const float*)d_in[8];
    float* out = (float*)d_out;

    // smem size in bytes (must match layout above)
    const size_t smem_bytes =
        (16 * HS + 16 * D_MODEL + 3 * (D_MODEL * HS) + 3 * D_MODEL +
         4 * D_MODEL + 4 * D_MODEL + 4 * 32 + 4 + 4 * D_MODEL) * sizeof(float);

    cudaFuncSetAttribute(fused_base_attention_kernel,
                         cudaFuncAttributeMaxDynamicSharedMemorySize,
                         (int)smem_bytes);

    precompute_mt_kernel<<<D_MODEL, D_MODEL>>>(Uq, Ur);
    fused_base_attention_kernel<<<BATCH / ROWS_PER_BLK, 256, smem_bytes>>>(
        obs, W1, b1, W2, b2, W3, b3, out);
}